// round 15
// baseline (speedup 1.0000x reference)
#include <cuda_runtime.h>
#include <cuda_fp16.h>
#include <cstdint>

#define NN 100000
#define NE 1600000
#define DIM 128

// ---- mma GEMM tile config ----
#define TILE_M 128
#define NTILES ((NN + TILE_M - 1) / TILE_M)   // 782
#define THR_LIN 1024
#define SAS_B 144                 // smem row stride in bytes (72 fp16)
#define OFF_AH 0
#define OFF_AL 18432
#define OFF_BH 36864
#define STAGE_B 55296             // bytes per pipeline stage (AH+AL+BH)
#define DYN_SMEM (2 * STAGE_B)    // 110592

// ---- k_pre block partition (conv + wt only now) ----
#define NB_CONV 12500             // NN*DIM/4 float4 / 256
#define NB_WT   256               // 2*128*256 / 256
#define GRID_PRE (NB_CONV + NB_WT)

// ---- fused CSR kernel ----
#define NBLK_CSR 148
#define NTHR_CSR 1024
#define CHUNK 676                 // ceil(NN/148)

// ---------------- scratch (no allocations allowed) ----------------
__device__ __half g_xhi[(size_t)NN * DIM];
__device__ __half g_xlo[(size_t)NN * DIM];
__device__ __half g_ahi[(size_t)NN * DIM];
__device__ __half g_alo[(size_t)NN * DIM];
__device__ __half g_hhi[(size_t)NN * DIM];
__device__ __half g_hlo[(size_t)NN * DIM];
__device__ __half g_wth[2][128 * 256];   // W^T fp16, [layer][n*256+k]
__device__ int g_rowptr[NN + 1];
__device__ int g_cursor[NN];
__device__ int g_col[NE];
__device__ int g_bsum[NBLK_CSR];
__device__ int g_boff[NBLK_CSR];
__device__ int g_count;           // sense-reversal barrier (self-resetting)
__device__ int g_sense;
__device__ int g_is64;

// ---------------- helpers ----------------
__device__ __forceinline__ uint32_t smem_u32(const void* p) {
    uint32_t a;
    asm("{ .reg .u64 t; cvta.to.shared.u64 t, %1; cvt.u32.u64 %0, t; }"
        : "=r"(a) : "l"(p));
    return a;
}
__device__ __forceinline__ void ldmx4(uint32_t* r, uint32_t addr) {
    asm volatile("ldmatrix.sync.aligned.m8n8.x4.shared.b16 {%0,%1,%2,%3}, [%4];"
                 : "=r"(r[0]), "=r"(r[1]), "=r"(r[2]), "=r"(r[3]) : "r"(addr));
}
__device__ __forceinline__ void mma16816(float* c, const uint32_t* a, const uint32_t* b) {
    asm volatile(
        "mma.sync.aligned.m16n8k16.row.col.f32.f16.f16.f32 "
        "{%0,%1,%2,%3}, {%4,%5,%6,%7}, {%8,%9}, {%0,%1,%2,%3};"
        : "+f"(c[0]), "+f"(c[1]), "+f"(c[2]), "+f"(c[3])
        : "r"(a[0]), "r"(a[1]), "r"(a[2]), "r"(a[3]), "r"(b[0]), "r"(b[1]));
}
// cp.async 16B; pred==0 -> zero-fill (src-size 0)
__device__ __forceinline__ void cpasync16(uint32_t dst, const void* src, int pred) {
    asm volatile("{\n\t.reg .pred p;\n\tsetp.ne.b32 p, %2, 0;\n\t"
                 "@p  cp.async.cg.shared.global [%0], [%1], 16;\n\t"
                 "@!p cp.async.cg.shared.global [%0], [%1], 16, 0;\n\t}"
                 :: "r"(dst), "l"(src), "r"(pred));
}
__device__ __forceinline__ void cp_commit() {
    asm volatile("cp.async.commit_group;" ::: "memory");
}
template <int N>
__device__ __forceinline__ void cp_wait() {
    asm volatile("cp.async.wait_group %0;" :: "n"(N) : "memory");
}
__device__ __forceinline__ int edge_at(const void* eiv, int idx) {
    if (g_is64) return (int)((const long long*)eiv)[idx];
    return ((const int*)eiv)[idx];
}
__device__ __forceinline__ uint32_t pack_h2(__half a, __half b) {
    return ((uint32_t)__half_as_ushort(b) << 16) | __half_as_ushort(a);
}
__device__ __forceinline__ void split_store4(__half* hp, __half* lp,
                                             float a, float b, float c, float d) {
    __half h0 = __float2half_rn(a), h1 = __float2half_rn(b);
    __half h2 = __float2half_rn(c), h3 = __float2half_rn(d);
    __half l0 = __float2half_rn(a - __half2float(h0));
    __half l1 = __float2half_rn(b - __half2float(h1));
    __half l2 = __float2half_rn(c - __half2float(h2));
    __half l3 = __float2half_rn(d - __half2float(h3));
    uint2 hv, lv;
    hv.x = pack_h2(h0, h1); hv.y = pack_h2(h2, h3);
    lv.x = pack_h2(l0, l1); lv.y = pack_h2(l2, l3);
    *(uint2*)hp = hv;
    *(uint2*)lp = lv;
}

// sense-reversing grid barrier: self-resetting, replay-safe (g_count returns
// to 0 after each use; g_sense just toggles). 148 co-resident blocks.
__device__ __forceinline__ void gbar() {
    __syncthreads();
    if (threadIdx.x == 0) {
        __threadfence();
        int s = atomicAdd(&g_sense, 0);
        int a = atomicAdd(&g_count, 1);
        if (a == NBLK_CSR - 1) {
            atomicExch(&g_count, 0);
            __threadfence();
            atomicExch(&g_sense, s ^ 1);
        } else {
            while (atomicAdd(&g_sense, 0) == s) {}
        }
        __threadfence();
    }
    __syncthreads();
}

// ---------------- pre: x split + W^T fp16 (independent of CSR) ----------------
__global__ void k_pre(const float* __restrict__ x,
                      const float* __restrict__ W1l, const float* __restrict__ W1r,
                      const float* __restrict__ W2l, const float* __restrict__ W2r) {
    int b = blockIdx.x, t = threadIdx.x;
    if (b < NB_CONV) {
        int i = b * 256 + t;                       // float4 index
        float4 v = ((const float4*)x)[i];
        split_store4(g_xhi + (size_t)i * 4, g_xlo + (size_t)i * 4, v.x, v.y, v.z, v.w);
    } else {
        int g = (b - NB_CONV) * 256 + t;
        int layer = g >> 15;
        int rem = g & 32767;
        int n = rem >> 8;
        int k = rem & 255;
        const float* W = layer ? (k < 128 ? W2l : W2r) : (k < 128 ? W1l : W1r);
        g_wth[layer][n * 256 + k] = __float2half_rn(W[(k & 127) * 128 + n]);
    }
}

// ---------------- fused CSR: zero + detect + hist + scan + fill ----------------
__global__ void __launch_bounds__(NTHR_CSR, 1) k_csr(const void* __restrict__ eiv) {
    int t = threadIdx.x, b = blockIdx.x;
    int gtid = b * NTHR_CSR + t;
    const int GS = NBLK_CSR * NTHR_CSR;
    __shared__ int wsum[32];
    int lane = t & 31, w = t >> 5;

    // phase 0: zero cursor + dtype detect
    for (int i = gtid; i < NN; i += GS) g_cursor[i] = 0;
    if (b == 0) {
        const int* e32 = (const int*)eiv;
        int nz = 0;
        for (int j = t; j < 4096; j += NTHR_CSR)
            if (e32[2 * j + 1] != 0) nz = 1;
        nz = __syncthreads_or(nz);
        if (t == 0) g_is64 = nz ? 0 : 1;
    }
    gbar();

    // phase 1: histogram
    for (int e = gtid; e < NE; e += GS)
        atomicAdd(&g_cursor[edge_at(eiv, NE + e)], 1);
    gbar();

    // phase 2: per-block local scan over CHUNK nodes
    int idx = b * CHUNK + t;
    int v = (t < CHUNK && idx < NN) ? g_cursor[idx] : 0;
    int s = v;
#pragma unroll
    for (int d = 1; d < 32; d <<= 1) {
        int o = __shfl_up_sync(0xffffffffu, s, d);
        if (lane >= d) s += o;
    }
    if (lane == 31) wsum[w] = s;
    __syncthreads();
    if (w == 0) {
        int ws = wsum[lane];
#pragma unroll
        for (int d = 1; d < 32; d <<= 1) {
            int o = __shfl_up_sync(0xffffffffu, ws, d);
            if (lane >= d) ws += o;
        }
        wsum[lane] = ws;
    }
    __syncthreads();
    int excl = (w ? wsum[w - 1] : 0) + s - v;
    if (t == 0) g_bsum[b] = wsum[31];
    __syncthreads();
    gbar();

    // phase 3: block 0 scans the 148 block sums
    if (b == 0) {
        int v2 = (t < NBLK_CSR) ? g_bsum[t] : 0;
        int s2 = v2;
#pragma unroll
        for (int d = 1; d < 32; d <<= 1) {
            int o = __shfl_up_sync(0xffffffffu, s2, d);
            if (lane >= d) s2 += o;
        }
        if (lane == 31) wsum[w] = s2;
        __syncthreads();
        if (w == 0) {
            int ws = wsum[lane];
#pragma unroll
            for (int d = 1; d < 32; d <<= 1) {
                int o = __shfl_up_sync(0xffffffffu, ws, d);
                if (lane >= d) ws += o;
            }
            wsum[lane] = ws;
        }
        __syncthreads();
        if (t < NBLK_CSR) g_boff[t] = (w ? wsum[w - 1] : 0) + s2 - v2;
    }
    if (gtid == 0) g_rowptr[NN] = NE;
    gbar();

    // phase 4: write rowptr + reset cursor to row start
    int boff = g_boff[b];
    if (t < CHUNK && idx < NN) {
        int r = excl + boff;
        g_rowptr[idx] = r;
        g_cursor[idx] = r;
    }
    gbar();

    // phase 5: fill adjacency
    for (int e = gtid; e < NE; e += GS) {
        int src = edge_at(eiv, e);
        int dst = edge_at(eiv, NE + e);
        g_col[atomicAdd(&g_cursor[dst], 1)] = src;
    }
}

// ---------------- mean aggregation over fp16 features (256B/row) ----------------
__global__ void __launch_bounds__(256) k_agg(const __half* __restrict__ feat) {
    int gw = (blockIdx.x * blockDim.x + threadIdx.x) >> 5;
    int lane = threadIdx.x & 31;
    if (gw >= NN) return;
    int beg = g_rowptr[gw];
    int end = g_rowptr[gw + 1];
    float4 acc = make_float4(0.f, 0.f, 0.f, 0.f);
    for (int base = beg; base < end; base += 32) {
        int navail = end - base;
        if (navail > 32) navail = 32;
        int cidx = (base + lane < end) ? g_col[base + lane] : 0;
        int j = 0;
        for (; j + 8 <= navail; j += 8) {
            uint2 vv[8];
#pragma unroll
            for (int u = 0; u < 8; u++) {
                int sv = __shfl_sync(0xffffffffu, cidx, j + u);
                vv[u] = *(const uint2*)(feat + (size_t)sv * DIM + lane * 4);
            }
#pragma unroll
            for (int u = 0; u < 8; u++) {
                float2 f0 = __half22float2(*(__half2*)&vv[u].x);
                float2 f1 = __half22float2(*(__half2*)&vv[u].y);
                acc.x += f0.x; acc.y += f0.y; acc.z += f1.x; acc.w += f1.y;
            }
        }
        for (; j < navail; j++) {
            int sv = __shfl_sync(0xffffffffu, cidx, j);
            uint2 vv = *(const uint2*)(feat + (size_t)sv * DIM + lane * 4);
            float2 f0 = __half22float2(*(__half2*)&vv.x);
            float2 f1 = __half22float2(*(__half2*)&vv.y);
            acc.x += f0.x; acc.y += f0.y; acc.z += f1.x; acc.w += f1.y;
        }
    }
    float inv = 1.0f / fmaxf((float)(end - beg), 1.0f);
    acc.x *= inv; acc.y *= inv; acc.z *= inv; acc.w *= inv;
    size_t o = (size_t)gw * DIM + lane * 4;
    split_store4(g_ahi + o, g_alo + o, acc.x, acc.y, acc.z, acc.w);
}

// ---------------- mma.sync fused linear, fp16 2-term, cp.async pipelined ----------
// D[128x128] = [agg | X](K=256, fp16 hi+lo) @ W^T(fp16) + b
// 1024 threads, 32 warps: wm = wid&7 (16 rows), wn = wid>>3 (32 cols).
__global__ void __launch_bounds__(THR_LIN, 1) k_lin_mma(
    const __half* __restrict__ Ahi, const __half* __restrict__ Alo,
    const __half* __restrict__ Xhi, const __half* __restrict__ Xlo,
    const __half* __restrict__ Bh,
    const float* __restrict__ bias, float* __restrict__ outf,
    __half* __restrict__ ohi, __half* __restrict__ olo, int do_relu) {
    extern __shared__ char dsm[];
    __shared__ float sbias[128];

    int tid = threadIdx.x;
    int wid = tid >> 5;
    int lane = tid & 31;
    int wm = wid & 7;
    int wn = wid >> 3;
    int n0 = blockIdx.x * TILE_M;

    uint32_t sbase = smem_u32(dsm);
    if (tid < 128) sbias[tid] = bias[tid];

    int a_off = (wm * 16 + (lane & 15)) * SAS_B + (lane >> 4) * 16;
    int b_off = (wn * 32 + (lane & 7) + ((lane >> 4) << 3)) * SAS_B + ((lane >> 3) & 1) * 16;

    float acc[4][4];
#pragma unroll
    for (int nt = 0; nt < 4; nt++)
#pragma unroll
        for (int p = 0; p < 4; p++) acc[nt][p] = 0.f;

    // stage issuer: chunk kc -> stage buffer sg (3 pieces: AH, AL, BH)
    auto stage_issue = [&](int kc, int sg) {
        const __half* ah = (kc < 2) ? Ahi : Xhi;
        const __half* al = (kc < 2) ? Alo : Xlo;
        int cb = (kc & 1) * 64;
        uint32_t sb = sbase + sg * STAGE_B;
#pragma unroll
        for (int it = 0; it < 3; it++) {
            int i = it * THR_LIN + tid;
            int piece = i >> 10;          // 0:AH 1:AL 2:BH
            int rem = i & 1023;
            int r = rem >> 3, c8 = rem & 7;
            uint32_t dst = sb + piece * 18432 + r * SAS_B + c8 * 16;
            if (piece < 2) {
                int gn = n0 + r;
                const __half* src = (piece == 0) ? ah : al;
                int gnc = (gn < NN) ? gn : 0;   // clamped ptr; size-0 if OOB
                cpasync16(dst, src + (size_t)gnc * DIM + cb + c8 * 8, gn < NN);
            } else {
                cpasync16(dst, Bh + (size_t)r * 256 + kc * 64 + c8 * 8, 1);
            }
        }
        cp_commit();
    };

    stage_issue(0, 0);

    for (int kc = 0; kc < 4; kc++) {
        if (kc < 3) stage_issue(kc + 1, (kc + 1) & 1);
        if (kc < 3) cp_wait<1>(); else cp_wait<0>();
        __syncthreads();

        uint32_t sb = sbase + (kc & 1) * STAGE_B;
        uint32_t Abh = sb + OFF_AH + a_off;
        uint32_t Abl = sb + OFF_AL + a_off;
        uint32_t Bb  = sb + OFF_BH + b_off;
#pragma unroll
        for (int ks = 0; ks < 4; ks++) {
            uint32_t ah_fr[4], al_fr[4];
            ldmx4(ah_fr, Abh + ks * 32);
            ldmx4(al_fr, Abl + ks * 32);
            uint32_t bfr[4][2];
#pragma unroll
            for (int bp = 0; bp < 2; bp++) {
                uint32_t q[4];
                ldmx4(q, Bb + ks * 32 + bp * 16 * SAS_B);
                bfr[2 * bp][0] = q[0]; bfr[2 * bp][1] = q[1];
                bfr[2 * bp + 1][0] = q[2]; bfr[2 * bp + 1][1] = q[3];
            }
#pragma unroll
            for (int nt = 0; nt < 4; nt++)
                mma16816(acc[nt], ah_fr, bfr[nt]);
#pragma unroll
            for (int nt = 0; nt < 4; nt++)
                mma16816(acc[nt], al_fr, bfr[nt]);
        }
        __syncthreads();
    }

    // epilogue: bias + relu; layer1 -> fp16 hi/lo, layer2 -> fp32 out
    int cbase = wn * 32 + (lane & 3) * 2;
    int r0 = n0 + wm * 16 + (lane >> 2);
#pragma unroll
    for (int nt = 0; nt < 4; nt++) {
        int c = cbase + nt * 8;
        float bx = sbias[c], by = sbias[c + 1];
#pragma unroll
        for (int half = 0; half < 2; half++) {
            int r = r0 + half * 8;
            if (r >= NN) continue;
            float vx = acc[nt][2 * half] + bx;
            float vy = acc[nt][2 * half + 1] + by;
            if (do_relu) { vx = fmaxf(vx, 0.f); vy = fmaxf(vy, 0.f); }
            size_t o = (size_t)r * DIM + c;
            if (outf) {
                *(float2*)(outf + o) = make_float2(vx, vy);
            } else {
                __half h0 = __float2half_rn(vx);
                __half h1 = __float2half_rn(vy);
                __half l0 = __float2half_rn(vx - __half2float(h0));
                __half l1 = __float2half_rn(vy - __half2float(h1));
                *(uint32_t*)(ohi + o) = pack_h2(h0, h1);
                *(uint32_t*)(olo + o) = pack_h2(l0, l1);
            }
        }
    }
}

// ---------------- launch ----------------
extern "C" void kernel_launch(void* const* d_in, const int* in_sizes, int n_in,
                              void* d_out, int out_size) {
    const float* x   = (const float*)d_in[0];
    const void*  ei  = d_in[1];
    const float* W1l = (const float*)d_in[2];
    const float* b1  = (const float*)d_in[3];
    const float* W1r = (const float*)d_in[4];
    const float* W2l = (const float*)d_in[5];
    const float* b2  = (const float*)d_in[6];
    const float* W2r = (const float*)d_in[7];
    float*       out = (float*)d_out;

    cudaFuncSetAttribute(k_lin_mma, cudaFuncAttributeMaxDynamicSharedMemorySize, DYN_SMEM);

    __half *xh, *xl, *ah, *al, *hh, *hl, *w1h, *w2h;
    cudaGetSymbolAddress((void**)&xh, g_xhi);
    cudaGetSymbolAddress((void**)&xl, g_xlo);
    cudaGetSymbolAddress((void**)&ah, g_ahi);
    cudaGetSymbolAddress((void**)&al, g_alo);
    cudaGetSymbolAddress((void**)&hh, g_hhi);
    cudaGetSymbolAddress((void**)&hl, g_hlo);
    {
        __half (*wth)[128 * 256];
        cudaGetSymbolAddress((void**)&wth, g_wth);
        w1h = wth[0]; w2h = wth[1];
    }

    // one-time stream/event setup (on the first, non-captured correctness call)
    static cudaStream_t s2 = nullptr;
    static cudaEvent_t evA = nullptr, evB = nullptr;
    if (!s2) {
        cudaStreamCreateWithFlags(&s2, cudaStreamNonBlocking);
        cudaEventCreateWithFlags(&evA, cudaEventDisableTiming);
        cudaEventCreateWithFlags(&evB, cudaEventDisableTiming);
    }

    int nb_w = (NN * 32) / 256;                // warp per node

    // fork: CSR build on s2, x/W conversion on the main stream, join before agg
    cudaEventRecord(evA, 0);
    cudaStreamWaitEvent(s2, evA, 0);
    k_csr<<<NBLK_CSR, NTHR_CSR, 0, s2>>>(ei);           // launch 0
    k_pre<<<GRID_PRE, 256>>>(x, W1l, W1r, W2l, W2r);    // launch 1 (main)
    cudaEventRecord(evB, s2);
    cudaStreamWaitEvent(0, evB, 0);

    // layer 1
    k_agg<<<nb_w, 256>>>(xh);                                                   // 2
    k_lin_mma<<<NTILES, THR_LIN, DYN_SMEM>>>(ah, al, xh, xl, w1h, b1,
                                             nullptr, hh, hl, 1);               // 3 <- ncu
    // layer 2
    k_agg<<<nb_w, 256>>>(hh);                                                   // 4
    k_lin_mma<<<NTILES, THR_LIN, DYN_SMEM>>>(ah, al, hh, hl, w2h, b2,
                                             out, nullptr, nullptr, 0);         // 5
}

// round 17
// speedup vs baseline: 1.3930x; 1.3930x over previous
#include <cuda_runtime.h>
#include <cuda_fp16.h>
#include <cstdint>

#define NN 100000
#define NE 1600000
#define DIM 128

// ---- mma GEMM tile config ----
#define TILE_M 128
#define NTILES ((NN + TILE_M - 1) / TILE_M)   // 782
#define THR_LIN 256
#define SAS_B 144                 // smem row stride in bytes (72 fp16)
#define OFF_AH 0
#define OFF_BH 18432
#define STAGE_B 36864             // bytes per pipeline stage (AH+BH)
#define NSTAGE 3
#define DYN_SMEM (NSTAGE * STAGE_B)   // 110592

// ---- k_pre block partition (conv + wt only) ----
#define NB_CONV 12500             // NN*DIM/4 float4 / 256
#define NB_WT   256               // 2*128*256 / 256
#define GRID_PRE (NB_CONV + NB_WT)

// ---- fused CSR kernel ----
#define NBLK_CSR 148
#define NTHR_CSR 1024
#define CHUNK 676                 // ceil(NN/148)

// ---------------- scratch (no allocations allowed) ----------------
__device__ __half g_xhi[(size_t)NN * DIM];
__device__ __half g_ahi[(size_t)NN * DIM];
__device__ __half g_hhi[(size_t)NN * DIM];
__device__ __half g_wth[2][128 * 256];   // W^T fp16, [layer][n*256+k]
__device__ int g_rowptr[NN + 1];
__device__ int g_cursor[NN];
__device__ int g_col[NE];
__device__ int g_bsum[NBLK_CSR];
__device__ int g_boff[NBLK_CSR];
__device__ int g_count;           // sense-reversal barrier (self-resetting)
__device__ int g_sense;
__device__ int g_is64;

// ---------------- helpers ----------------
__device__ __forceinline__ uint32_t smem_u32(const void* p) {
    uint32_t a;
    asm("{ .reg .u64 t; cvta.to.shared.u64 t, %1; cvt.u32.u64 %0, t; }"
        : "=r"(a) : "l"(p));
    return a;
}
__device__ __forceinline__ void ldmx4(uint32_t* r, uint32_t addr) {
    asm volatile("ldmatrix.sync.aligned.m8n8.x4.shared.b16 {%0,%1,%2,%3}, [%4];"
                 : "=r"(r[0]), "=r"(r[1]), "=r"(r[2]), "=r"(r[3]) : "r"(addr));
}
__device__ __forceinline__ void mma16816(float* c, const uint32_t* a, const uint32_t* b) {
    asm volatile(
        "mma.sync.aligned.m16n8k16.row.col.f32.f16.f16.f32 "
        "{%0,%1,%2,%3}, {%4,%5,%6,%7}, {%8,%9}, {%0,%1,%2,%3};"
        : "+f"(c[0]), "+f"(c[1]), "+f"(c[2]), "+f"(c[3])
        : "r"(a[0]), "r"(a[1]), "r"(a[2]), "r"(a[3]), "r"(b[0]), "r"(b[1]));
}
// cp.async 16B; pred==0 -> zero-fill (src-size 0)
__device__ __forceinline__ void cpasync16(uint32_t dst, const void* src, int pred) {
    asm volatile("{\n\t.reg .pred p;\n\tsetp.ne.b32 p, %2, 0;\n\t"
                 "@p  cp.async.cg.shared.global [%0], [%1], 16;\n\t"
                 "@!p cp.async.cg.shared.global [%0], [%1], 16, 0;\n\t}"
                 :: "r"(dst), "l"(src), "r"(pred));
}
__device__ __forceinline__ void cp_commit() {
    asm volatile("cp.async.commit_group;" ::: "memory");
}
template <int N>
__device__ __forceinline__ void cp_wait() {
    asm volatile("cp.async.wait_group %0;" :: "n"(N) : "memory");
}
__device__ __forceinline__ int edge_at(const void* eiv, int idx) {
    if (g_is64) return (int)((const long long*)eiv)[idx];
    return ((const int*)eiv)[idx];
}
__device__ __forceinline__ uint32_t pack_h2(__half a, __half b) {
    return ((uint32_t)__half_as_ushort(b) << 16) | __half_as_ushort(a);
}
__device__ __forceinline__ void store_h4(__half* hp, float a, float b, float c, float d) {
    uint2 hv;
    hv.x = pack_h2(__float2half_rn(a), __float2half_rn(b));
    hv.y = pack_h2(__float2half_rn(c), __float2half_rn(d));
    *(uint2*)hp = hv;
}

// sense-reversing grid barrier: self-resetting, replay-safe.
__device__ __forceinline__ void gbar() {
    __syncthreads();
    if (threadIdx.x == 0) {
        __threadfence();
        int s = atomicAdd(&g_sense, 0);
        int a = atomicAdd(&g_count, 1);
        if (a == NBLK_CSR - 1) {
            atomicExch(&g_count, 0);
            __threadfence();
            atomicExch(&g_sense, s ^ 1);
        } else {
            while (atomicAdd(&g_sense, 0) == s) {}
        }
        __threadfence();
    }
    __syncthreads();
}

// ---------------- pre: x -> fp16 + W^T fp16 (independent of CSR) ----------------
__global__ void k_pre(const float* __restrict__ x,
                      const float* __restrict__ W1l, const float* __restrict__ W1r,
                      const float* __restrict__ W2l, const float* __restrict__ W2r) {
    int b = blockIdx.x, t = threadIdx.x;
    if (b < NB_CONV) {
        int i = b * 256 + t;                       // float4 index
        float4 v = ((const float4*)x)[i];
        store_h4(g_xhi + (size_t)i * 4, v.x, v.y, v.z, v.w);
    } else {
        int g = (b - NB_CONV) * 256 + t;
        int layer = g >> 15;
        int rem = g & 32767;
        int n = rem >> 8;
        int k = rem & 255;
        const float* W = layer ? (k < 128 ? W2l : W2r) : (k < 128 ? W1l : W1r);
        g_wth[layer][n * 256 + k] = __float2half_rn(W[(k & 127) * 128 + n]);
    }
}

// ---------------- fused CSR: zero + detect + hist + scan + fill ----------------
__global__ void __launch_bounds__(NTHR_CSR, 1) k_csr(const void* __restrict__ eiv) {
    int t = threadIdx.x, b = blockIdx.x;
    int gtid = b * NTHR_CSR + t;
    const int GS = NBLK_CSR * NTHR_CSR;
    __shared__ int wsum[32];
    int lane = t & 31, w = t >> 5;

    for (int i = gtid; i < NN; i += GS) g_cursor[i] = 0;
    if (b == 0) {
        const int* e32 = (const int*)eiv;
        int nz = 0;
        for (int j = t; j < 4096; j += NTHR_CSR)
            if (e32[2 * j + 1] != 0) nz = 1;
        nz = __syncthreads_or(nz);
        if (t == 0) g_is64 = nz ? 0 : 1;
    }
    gbar();

    for (int e = gtid; e < NE; e += GS)
        atomicAdd(&g_cursor[edge_at(eiv, NE + e)], 1);
    gbar();

    int idx = b * CHUNK + t;
    int v = (t < CHUNK && idx < NN) ? g_cursor[idx] : 0;
    int s = v;
#pragma unroll
    for (int d = 1; d < 32; d <<= 1) {
        int o = __shfl_up_sync(0xffffffffu, s, d);
        if (lane >= d) s += o;
    }
    if (lane == 31) wsum[w] = s;
    __syncthreads();
    if (w == 0) {
        int ws = wsum[lane];
#pragma unroll
        for (int d = 1; d < 32; d <<= 1) {
            int o = __shfl_up_sync(0xffffffffu, ws, d);
            if (lane >= d) ws += o;
        }
        wsum[lane] = ws;
    }
    __syncthreads();
    int excl = (w ? wsum[w - 1] : 0) + s - v;
    if (t == 0) g_bsum[b] = wsum[31];
    __syncthreads();
    gbar();

    if (b == 0) {
        int v2 = (t < NBLK_CSR) ? g_bsum[t] : 0;
        int s2 = v2;
#pragma unroll
        for (int d = 1; d < 32; d <<= 1) {
            int o = __shfl_up_sync(0xffffffffu, s2, d);
            if (lane >= d) s2 += o;
        }
        if (lane == 31) wsum[w] = s2;
        __syncthreads();
        if (w == 0) {
            int ws = wsum[lane];
#pragma unroll
            for (int d = 1; d < 32; d <<= 1) {
                int o = __shfl_up_sync(0xffffffffu, ws, d);
                if (lane >= d) ws += o;
            }
            wsum[lane] = ws;
        }
        __syncthreads();
        if (t < NBLK_CSR) g_boff[t] = (w ? wsum[w - 1] : 0) + s2 - v2;
    }
    if (gtid == 0) g_rowptr[NN] = NE;
    gbar();

    int boff = g_boff[b];
    if (t < CHUNK && idx < NN) {
        int r = excl + boff;
        g_rowptr[idx] = r;
        g_cursor[idx] = r;
    }
    gbar();

    for (int e = gtid; e < NE; e += GS) {
        int src = edge_at(eiv, e);
        int dst = edge_at(eiv, NE + e);
        g_col[atomicAdd(&g_cursor[dst], 1)] = src;
    }
}

// ---------------- mean aggregation over fp16 features, fp16-hi out ----------------
__global__ void __launch_bounds__(256) k_agg(const __half* __restrict__ feat) {
    int gw = (blockIdx.x * blockDim.x + threadIdx.x) >> 5;
    int lane = threadIdx.x & 31;
    if (gw >= NN) return;
    int beg = g_rowptr[gw];
    int end = g_rowptr[gw + 1];
    float4 acc = make_float4(0.f, 0.f, 0.f, 0.f);
    for (int base = beg; base < end; base += 32) {
        int navail = end - base;
        if (navail > 32) navail = 32;
        int cidx = (base + lane < end) ? g_col[base + lane] : 0;
        int j = 0;
        for (; j + 8 <= navail; j += 8) {
            uint2 vv[8];
#pragma unroll
            for (int u = 0; u < 8; u++) {
                int sv = __shfl_sync(0xffffffffu, cidx, j + u);
                vv[u] = *(const uint2*)(feat + (size_t)sv * DIM + lane * 4);
            }
#pragma unroll
            for (int u = 0; u < 8; u++) {
                float2 f0 = __half22float2(*(__half2*)&vv[u].x);
                float2 f1 = __half22float2(*(__half2*)&vv[u].y);
                acc.x += f0.x; acc.y += f0.y; acc.z += f1.x; acc.w += f1.y;
            }
        }
        for (; j < navail; j++) {
            int sv = __shfl_sync(0xffffffffu, cidx, j);
            uint2 vv = *(const uint2*)(feat + (size_t)sv * DIM + lane * 4);
            float2 f0 = __half22float2(*(__half2*)&vv.x);
            float2 f1 = __half22float2(*(__half2*)&vv.y);
            acc.x += f0.x; acc.y += f0.y; acc.z += f1.x; acc.w += f1.y;
        }
    }
    float inv = 1.0f / fmaxf((float)(end - beg), 1.0f);
    store_h4(g_ahi + (size_t)gw * DIM + lane * 4,
             acc.x * inv, acc.y * inv, acc.z * inv, acc.w * inv);
}

// ---------------- mma.sync fused linear, fp16 1-term, 3-stage cp.async -----------
// D[128x128] = [agg | X](K=256, fp16) @ W^T(fp16) + b
// 256 threads, 8 warps: wm = wid&3 (32 rows), wn = wid>>2 (64 cols). 2 CTAs/SM.
__global__ void __launch_bounds__(THR_LIN, 2) k_lin_mma(
    const __half* __restrict__ Ahi, const __half* __restrict__ Xhi,
    const __half* __restrict__ Bh,
    const float* __restrict__ bias, float* __restrict__ outf,
    __half* __restrict__ ohi, int do_relu) {
    extern __shared__ char dsm[];
    __shared__ float sbias[128];

    int tid = threadIdx.x;
    int wid = tid >> 5;
    int lane = tid & 31;
    int wm = wid & 3;
    int wn = wid >> 2;
    int n0 = blockIdx.x * TILE_M;

    uint32_t sbase = smem_u32(dsm);
    if (tid < 128) sbias[tid] = bias[tid];

    // A: two m16 tiles at rows wm*32 and wm*32+16
    int a_off = (wm * 32 + (lane & 15)) * SAS_B + (lane >> 4) * 16;
    int b_off = (wn * 64 + (lane & 7) + ((lane >> 4) << 3)) * SAS_B + ((lane >> 3) & 1) * 16;

    float acc[2][8][4];
#pragma unroll
    for (int mt = 0; mt < 2; mt++)
#pragma unroll
        for (int nt = 0; nt < 8; nt++)
#pragma unroll
            for (int p = 0; p < 4; p++) acc[mt][nt][p] = 0.f;

    // stage issuer: chunk kc -> stage buffer sg (2 pieces: AH, BH)
    auto stage_issue = [&](int kc, int sg) {
        const __half* ah = (kc < 2) ? Ahi : Xhi;
        int cb = (kc & 1) * 64;
        uint32_t sb = sbase + sg * STAGE_B;
#pragma unroll
        for (int it = 0; it < 8; it++) {
            int i = it * THR_LIN + tid;
            int piece = i >> 10;          // 0:AH 1:BH
            int rem = i & 1023;
            int r = rem >> 3, c8 = rem & 7;
            uint32_t dst = sb + piece * 18432 + r * SAS_B + c8 * 16;
            if (piece == 0) {
                int gn = n0 + r;
                int gnc = (gn < NN) ? gn : 0;   // clamped ptr; size-0 if OOB
                cpasync16(dst, ah + (size_t)gnc * DIM + cb + c8 * 8, gn < NN);
            } else {
                cpasync16(dst, Bh + (size_t)r * 256 + kc * 64 + c8 * 8, 1);
            }
        }
        cp_commit();
    };

    stage_issue(0, 0);
    stage_issue(1, 1);

    for (int kc = 0; kc < 4; kc++) {
        if (kc < 3) cp_wait<1>(); else cp_wait<0>();
        __syncthreads();

        uint32_t sb = sbase + (kc % NSTAGE) * STAGE_B;
        uint32_t Ab = sb + OFF_AH + a_off;
        uint32_t Bb = sb + OFF_BH + b_off;
#pragma unroll
        for (int ks = 0; ks < 4; ks++) {
            uint32_t afr[2][4];
            ldmx4(afr[0], Ab + ks * 32);
            ldmx4(afr[1], Ab + ks * 32 + 16 * SAS_B);
            uint32_t bfr[8][2];
#pragma unroll
            for (int bp = 0; bp < 4; bp++) {
                uint32_t q[4];
                ldmx4(q, Bb + ks * 32 + bp * 16 * SAS_B);
                bfr[2 * bp][0] = q[0]; bfr[2 * bp][1] = q[1];
                bfr[2 * bp + 1][0] = q[2]; bfr[2 * bp + 1][1] = q[3];
            }
#pragma unroll
            for (int mt = 0; mt < 2; mt++)
#pragma unroll
                for (int nt = 0; nt < 8; nt++)
                    mma16816(acc[mt][nt], afr[mt], bfr[nt]);
        }
        __syncthreads();
        if (kc + 2 < 4) stage_issue(kc + 2, (kc + 2) % NSTAGE);
    }

    // epilogue: bias + relu; layer1 -> fp16, layer2 -> fp32 out
    int cbase = wn * 64 + (lane & 3) * 2;
#pragma unroll
    for (int mt = 0; mt < 2; mt++) {
        int r0 = n0 + wm * 32 + mt * 16 + (lane >> 2);
#pragma unroll
        for (int nt = 0; nt < 8; nt++) {
            int c = cbase + nt * 8;
            float bx = sbias[c], by = sbias[c + 1];
#pragma unroll
            for (int half = 0; half < 2; half++) {
                int r = r0 + half * 8;
                if (r >= NN) continue;
                float vx = acc[mt][nt][2 * half] + bx;
                float vy = acc[mt][nt][2 * half + 1] + by;
                if (do_relu) { vx = fmaxf(vx, 0.f); vy = fmaxf(vy, 0.f); }
                size_t o = (size_t)r * DIM + c;
                if (outf) {
                    *(float2*)(outf + o) = make_float2(vx, vy);
                } else {
                    *(uint32_t*)(ohi + o) = pack_h2(__float2half_rn(vx),
                                                    __float2half_rn(vy));
                }
            }
        }
    }
}

// ---------------- launch ----------------
extern "C" void kernel_launch(void* const* d_in, const int* in_sizes, int n_in,
                              void* d_out, int out_size) {
    const float* x   = (const float*)d_in[0];
    const void*  ei  = d_in[1];
    const float* W1l = (const float*)d_in[2];
    const float* b1  = (const float*)d_in[3];
    const float* W1r = (const float*)d_in[4];
    const float* W2l = (const float*)d_in[5];
    const float* b2  = (const float*)d_in[6];
    const float* W2r = (const float*)d_in[7];
    float*       out = (float*)d_out;

    cudaFuncSetAttribute(k_lin_mma, cudaFuncAttributeMaxDynamicSharedMemorySize, DYN_SMEM);

    __half *xh, *ah, *hh, *w1h, *w2h;
    cudaGetSymbolAddress((void**)&xh, g_xhi);
    cudaGetSymbolAddress((void**)&ah, g_ahi);
    cudaGetSymbolAddress((void**)&hh, g_hhi);
    {
        __half (*wth)[128 * 256];
        cudaGetSymbolAddress((void**)&wth, g_wth);
        w1h = wth[0]; w2h = wth[1];
    }

    // one-time stream/event setup (on the first, non-captured correctness call)
    static cudaStream_t s2 = nullptr;
    static cudaEvent_t evA = nullptr, evB = nullptr;
    if (!s2) {
        cudaStreamCreateWithFlags(&s2, cudaStreamNonBlocking);
        cudaEventCreateWithFlags(&evA, cudaEventDisableTiming);
        cudaEventCreateWithFlags(&evB, cudaEventDisableTiming);
    }

    int nb_w = (NN * 32) / 256;                // warp per node

    // fork: CSR build on s2, x/W conversion on the main stream, join before agg
    cudaEventRecord(evA, 0);
    cudaStreamWaitEvent(s2, evA, 0);
    k_csr<<<NBLK_CSR, NTHR_CSR, 0, s2>>>(ei);           // launch 0
    k_pre<<<GRID_PRE, 256>>>(x, W1l, W1r, W2l, W2r);    // launch 1 (main)
    cudaEventRecord(evB, s2);
    cudaStreamWaitEvent(0, evB, 0);

    // layer 1
    k_agg<<<nb_w, 256>>>(xh);                                                   // 2
    k_lin_mma<<<NTILES, THR_LIN, DYN_SMEM>>>(ah, xh, w1h, b1,
                                             nullptr, hh, 1);                   // 3 <- ncu
    // layer 2
    k_agg<<<nb_w, 256>>>(hh);                                                   // 4
    k_lin_mma<<<NTILES, THR_LIN, DYN_SMEM>>>(ah, hh, w2h, b2,
                                             out, nullptr, 0);                  // 5
}